// round 2
// baseline (speedup 1.0000x reference)
#include <cuda_runtime.h>
#include <cuda_bf16.h>
#include <cstddef>

// Problem constants (fixed by the reference setup)
constexpr int B   = 16;
constexpr int TM  = 128;
constexpr int SM  = 64;
constexpr int SP1 = SM + 1;            // 65
constexpr int V   = 1024;
constexpr int NROWS = B * TM * SP1;    // 133120

#define NEGV (-1e30f)

// Scratch (device globals: no allocation allowed in kernel_launch)
__device__ float g_blp[NROWS];   // blank log-prob per row
__device__ float g_llp[NROWS];   // label log-prob per row (NEG where s == SM)

// ---------------------------------------------------------------------------
// Kernel A: per-row logsumexp + extraction of blank / label log-probs.
// One warp per row. Each lane loads 8 float4 (32 floats) -> 1024 per warp.
// Fully coalesced: lane i reads float4 index j*32+i.
// ---------------------------------------------------------------------------
__global__ void __launch_bounds__(256)
lse_kernel(const float* __restrict__ acts, const int* __restrict__ labels)
{
    const int warps_per_blk = blockDim.x >> 5;
    const int row  = blockIdx.x * warps_per_blk + (threadIdx.x >> 5);
    const int lane = threadIdx.x & 31;
    if (row >= NROWS) return;

    const float4* p = reinterpret_cast<const float4*>(acts) + (size_t)row * (V / 4);

    float4 v[8];
#pragma unroll
    for (int j = 0; j < 8; j++) v[j] = p[j * 32 + lane];

    // thread-local max
    float m = v[0].x;
#pragma unroll
    for (int j = 0; j < 8; j++) {
        m = fmaxf(m, fmaxf(fmaxf(v[j].x, v[j].y), fmaxf(v[j].z, v[j].w)));
    }
    // thread-local exp-sum
    float s = 0.f;
#pragma unroll
    for (int j = 0; j < 8; j++) {
        s += __expf(v[j].x - m) + __expf(v[j].y - m)
           + __expf(v[j].z - m) + __expf(v[j].w - m);
    }
    // warp reduction of (max, sum) pairs
#pragma unroll
    for (int off = 16; off > 0; off >>= 1) {
        float mo = __shfl_xor_sync(0xffffffffu, m, off);
        float so = __shfl_xor_sync(0xffffffffu, s, off);
        float M  = fmaxf(m, mo);
        s = s * __expf(m - M) + so * __expf(mo - M);
        m = M;
    }

    if (lane == 0) {
        const float lse = m + __logf(s);
        const int b    = row / (TM * SP1);
        const int rem  = row % (TM * SP1);
        const int sidx = rem % SP1;

        // acts[row, 0] is v[0].x on lane 0
        g_blp[row] = v[0].x - lse;

        float ll = NEGV;
        if (sidx < SM) {
            const int lab = labels[b * SM + sidx];
            // row was just streamed by this warp -> L1 hit
            ll = __ldg(acts + (size_t)row * V + lab) - lse;
        }
        g_llp[row] = ll;
    }
}

// ---------------------------------------------------------------------------
// Kernel B: alpha recursion. One CTA per batch.
// Stage the whole (T, S+1) blp/llp tile into dynamic smem (66 KB), then run
// the 128 serial steps entirely out of shared memory.
// ---------------------------------------------------------------------------
__global__ void __launch_bounds__(128)
alpha_kernel(const int* __restrict__ input_lengths,
             const int* __restrict__ label_lengths,
             float* __restrict__ out)
{
    extern __shared__ float smem[];
    float* blp_s = smem;                 // TM*SP1
    float* llp_s = smem + TM * SP1;      // TM*SP1
    __shared__ float alpha[SP1];

    const int b   = blockIdx.x;
    const int tid = threadIdx.x;

    const float* gb = g_blp + (size_t)b * TM * SP1;
    const float* gl = g_llp + (size_t)b * TM * SP1;
    for (int i = tid; i < TM * SP1; i += blockDim.x) {
        blp_s[i] = gb[i];
        llp_s[i] = gl[i];
    }
    if (tid < SP1) alpha[tid] = (tid == 0) ? 0.f : NEGV;

    const int Tb = input_lengths[b];
    const int Sb = label_lengths[b];
    __syncthreads();

    for (int t = 0; t < Tb; t++) {
        float nv = 0.f;
        if (tid < SP1) {
            const float a  = alpha[tid] + blp_s[t * SP1 + tid];
            const float sh = (tid == 0) ? NEGV
                                        : alpha[tid - 1] + llp_s[t * SP1 + tid - 1];
            const float mx = fmaxf(a, sh);
            const float mn = fminf(a, sh);
            nv = mx + log1pf(__expf(mn - mx));
        }
        __syncthreads();
        if (tid < SP1 && tid <= Sb) alpha[tid] = nv;
        __syncthreads();
    }

    if (tid == 0) out[b] = -alpha[Sb];
}

// ---------------------------------------------------------------------------
extern "C" void kernel_launch(void* const* d_in, const int* in_sizes, int n_in,
                              void* d_out, int out_size)
{
    const float* acts   = (const float*)d_in[0];
    const int*   labels = (const int*)d_in[1];
    const int*   ilen   = (const int*)d_in[2];
    const int*   llen   = (const int*)d_in[3];
    float*       out    = (float*)d_out;

    // Kernel A: 8 warps (8 rows) per 256-thread block
    const int rows_per_blk = 8;
    const int gridA = (NROWS + rows_per_blk - 1) / rows_per_blk;
    lse_kernel<<<gridA, 256>>>(acts, labels);

    // Kernel B: 66 KB dynamic smem (> 48 KB default -> opt in)
    const size_t smemB = (size_t)2 * TM * SP1 * sizeof(float);
    cudaFuncSetAttribute(alpha_kernel,
                         cudaFuncAttributeMaxDynamicSharedMemorySize,
                         (int)smemB);
    alpha_kernel<<<B, 128, smemB>>>(ilen, llen, out);
}

// round 3
// speedup vs baseline: 1.0921x; 1.0921x over previous
#include <cuda_runtime.h>
#include <cuda_bf16.h>
#include <cstddef>

// Problem constants (fixed by the reference setup)
constexpr int B   = 16;
constexpr int TM  = 128;
constexpr int SM  = 64;
constexpr int SP1 = SM + 1;            // 65
constexpr int V   = 1024;
constexpr int NROWS = B * TM * SP1;    // 133120

#define NEGV (-1e30f)

// Scratch (device globals: no allocation allowed in kernel_launch)
__device__ float g_blp[NROWS];   // blank log-prob per row
__device__ float g_llp[NROWS];   // label log-prob per row (NEG where s == SM)

// ---------------------------------------------------------------------------
// Kernel A: per-row logsumexp + extraction of blank / label log-probs.
// One warp per row. Each lane loads 8 float4 (32 floats) -> 1024 per warp.
// ---------------------------------------------------------------------------
__global__ void __launch_bounds__(256)
lse_kernel(const float* __restrict__ acts, const int* __restrict__ labels)
{
    const int warps_per_blk = blockDim.x >> 5;
    const int row  = blockIdx.x * warps_per_blk + (threadIdx.x >> 5);
    const int lane = threadIdx.x & 31;
    if (row >= NROWS) return;

    const float4* p = reinterpret_cast<const float4*>(acts) + (size_t)row * (V / 4);

    float4 v[8];
#pragma unroll
    for (int j = 0; j < 8; j++) v[j] = p[j * 32 + lane];

    float m = v[0].x;
#pragma unroll
    for (int j = 0; j < 8; j++) {
        m = fmaxf(m, fmaxf(fmaxf(v[j].x, v[j].y), fmaxf(v[j].z, v[j].w)));
    }
    float s = 0.f;
#pragma unroll
    for (int j = 0; j < 8; j++) {
        s += __expf(v[j].x - m) + __expf(v[j].y - m)
           + __expf(v[j].z - m) + __expf(v[j].w - m);
    }
#pragma unroll
    for (int off = 16; off > 0; off >>= 1) {
        float mo = __shfl_xor_sync(0xffffffffu, m, off);
        float so = __shfl_xor_sync(0xffffffffu, s, off);
        float M  = fmaxf(m, mo);
        s = s * __expf(m - M) + so * __expf(mo - M);
        m = M;
    }

    if (lane == 0) {
        const float lse = m + __logf(s);
        const int b    = row / (TM * SP1);
        const int rem  = row % (TM * SP1);
        const int sidx = rem % SP1;

        g_blp[row] = v[0].x - lse;   // acts[row, 0]

        float ll = NEGV;
        if (sidx < SM) {
            const int lab = labels[b * SM + sidx];
            ll = __ldg(acts + (size_t)row * V + lab) - lse;   // L1 hit
        }
        g_llp[row] = ll;
    }
}

// ---------------------------------------------------------------------------
// logaddexp via fast MUFU path
// ---------------------------------------------------------------------------
__device__ __forceinline__ float lse2(float x, float y)
{
    const float mx = fmaxf(x, y);
    const float mn = fminf(x, y);
    return mx + __logf(1.0f + __expf(mn - mx));
}

// ---------------------------------------------------------------------------
// Kernel B: alpha recursion. One CTA per batch.
// 128 threads stage the (T, S+1) blp/llp tile into smem (float4); then
// warp 0 runs the 128-step recursion entirely in registers:
//   lane l holds alpha[l] (lo) and alpha[32+l] (hi); alpha[64] is replicated
//   across all lanes (all inputs to it are warp-uniform broadcasts).
// Neighbor dependency alpha[s-1] via shfl_up — no barriers in the loop.
// ---------------------------------------------------------------------------
__global__ void __launch_bounds__(128)
alpha_kernel(const int* __restrict__ input_lengths,
             const int* __restrict__ label_lengths,
             float* __restrict__ out)
{
    extern __shared__ float smem[];
    float* blp_s = smem;                 // TM*SP1 = 8320 floats
    float* llp_s = smem + TM * SP1;

    const int b   = blockIdx.x;
    const int tid = threadIdx.x;

    // Cooperative staged load (vectorized; 8320 floats = 2080 float4 per array)
    {
        const float4* gb4 = reinterpret_cast<const float4*>(g_blp + (size_t)b * TM * SP1);
        const float4* gl4 = reinterpret_cast<const float4*>(g_llp + (size_t)b * TM * SP1);
        float4* sb4 = reinterpret_cast<float4*>(blp_s);
        float4* sl4 = reinterpret_cast<float4*>(llp_s);
        constexpr int N4 = TM * SP1 / 4;   // 2080
        for (int i = tid; i < N4; i += 128) {
            sb4[i] = gb4[i];
            sl4[i] = gl4[i];
        }
    }
    __syncthreads();

    if (tid >= 32) return;               // recursion lives in warp 0
    const int l = tid;
    const unsigned FULL = 0xffffffffu;

    const int Tb = input_lengths[b];
    const int Sb = label_lengths[b];

    float a_lo  = (l == 0) ? 0.f : NEGV;   // alpha[l]
    float a_hi  = NEGV;                    // alpha[32+l]
    float a_top = NEGV;                    // alpha[64] (warp-uniform)

    for (int t = 0; t < Tb; t++) {
        const float* bt = blp_s + t * SP1;
        const float* lt = llp_s + t * SP1;

        // smem operands (issue early; broadcast or conflict-free)
        const float b_lo  = bt[l];
        const float b_hi  = bt[l + 32];
        const float b_top = bt[64];
        const float ll_m1 = lt[(l == 0) ? 0 : (l - 1)];  // llp[s-1] for s=l
        const float ll_h  = lt[l + 31];                  // llp[s-1] for s=32+l
        const float ll_t  = lt[63];                      // llp[63]

        // old-alpha neighbor values
        const float pa_lo = __shfl_up_sync(FULL, a_lo, 1);
        const float la_lo = __shfl_sync(FULL, a_lo, 31);   // alpha[31]
        const float pa_hi = __shfl_up_sync(FULL, a_hi, 1);
        const float la_hi = __shfl_sync(FULL, a_hi, 31);   // alpha[63]

        const float sh_lo = (l == 0) ? NEGV : (pa_lo + ll_m1);
        const float sh_hi = ((l == 0) ? la_lo : pa_hi) + ll_h;
        const float sh_tp = la_hi + ll_t;

        const float d_lo = a_lo + b_lo;
        const float d_hi = a_hi + b_hi;
        const float d_tp = a_top + b_top;

        a_lo  = lse2(d_lo, sh_lo);
        a_hi  = lse2(d_hi, sh_hi);
        a_top = lse2(d_tp, sh_tp);         // warp-uniform, no divergence
    }

    // select alpha[Sb]
    float res;
    if (Sb >= 64)      res = a_top;
    else if (Sb >= 32) res = __shfl_sync(FULL, a_hi, Sb - 32);
    else               res = __shfl_sync(FULL, a_lo, Sb);

    if (l == 0) out[b] = -res;
}

// ---------------------------------------------------------------------------
extern "C" void kernel_launch(void* const* d_in, const int* in_sizes, int n_in,
                              void* d_out, int out_size)
{
    const float* acts   = (const float*)d_in[0];
    const int*   labels = (const int*)d_in[1];
    const int*   ilen   = (const int*)d_in[2];
    const int*   llen   = (const int*)d_in[3];
    float*       out    = (float*)d_out;

    const int rows_per_blk = 8;
    const int gridA = (NROWS + rows_per_blk - 1) / rows_per_blk;
    lse_kernel<<<gridA, 256>>>(acts, labels);

    const size_t smemB = (size_t)2 * TM * SP1 * sizeof(float);  // 66560 B
    cudaFuncSetAttribute(alpha_kernel,
                         cudaFuncAttributeMaxDynamicSharedMemorySize,
                         (int)smemB);
    alpha_kernel<<<B, 128, smemB>>>(ilen, llen, out);
}

// round 5
// speedup vs baseline: 1.1173x; 1.0231x over previous
#include <cuda_runtime.h>
#include <cuda_bf16.h>
#include <cstddef>

// Problem constants (fixed by the reference setup)
constexpr int B   = 16;
constexpr int TM  = 128;
constexpr int SM  = 64;
constexpr int SP1 = SM + 1;            // 65
constexpr int V   = 1024;
constexpr int NROWS = B * TM * SP1;    // 133120

// Scratch in EXP space (device globals: no allocation in kernel_launch)
__device__ float g_eb[NROWS];   // exp(blank_lp) per row
__device__ float g_el[NROWS];   // exp(label_lp) per row (0 where s == SM)

// ---------------------------------------------------------------------------
// Kernel A: per-row logsumexp; writes exp-space blank/label probabilities.
// One warp per row; 8x float4 per lane; HBM-bound (~7.1 TB/s achieved).
// ---------------------------------------------------------------------------
__global__ void __launch_bounds__(256)
lse_kernel(const float* __restrict__ acts, const int* __restrict__ labels)
{
    const int warps_per_blk = blockDim.x >> 5;
    const int row  = blockIdx.x * warps_per_blk + (threadIdx.x >> 5);
    const int lane = threadIdx.x & 31;
    if (row >= NROWS) return;

    const float4* p = reinterpret_cast<const float4*>(acts) + (size_t)row * (V / 4);

    float4 v[8];
#pragma unroll
    for (int j = 0; j < 8; j++) v[j] = p[j * 32 + lane];

    float m = v[0].x;
#pragma unroll
    for (int j = 0; j < 8; j++) {
        m = fmaxf(m, fmaxf(fmaxf(v[j].x, v[j].y), fmaxf(v[j].z, v[j].w)));
    }
    float s = 0.f;
#pragma unroll
    for (int j = 0; j < 8; j++) {
        s += __expf(v[j].x - m) + __expf(v[j].y - m)
           + __expf(v[j].z - m) + __expf(v[j].w - m);
    }
#pragma unroll
    for (int off = 16; off > 0; off >>= 1) {
        float mo = __shfl_xor_sync(0xffffffffu, m, off);
        float so = __shfl_xor_sync(0xffffffffu, s, off);
        float M  = fmaxf(m, mo);
        s = s * __expf(m - M) + so * __expf(mo - M);
        m = M;
    }

    if (lane == 0) {
        const float lse = m + __logf(s);
        const int b    = row / (TM * SP1);
        const int rem  = row % (TM * SP1);
        const int sidx = rem % SP1;

        g_eb[row] = __expf(v[0].x - lse);   // exp(blank - lse)

        float el = 0.f;
        if (sidx < SM) {
            const int lab = labels[b * SM + sidx];
            el = __expf(__ldg(acts + (size_t)row * V + lab) - lse);  // L1 hit
        }
        g_el[row] = el;
    }
}

// ---------------------------------------------------------------------------
// Kernel B: alpha recursion in probability space. One CTA per batch.
// Warp 0 holds A[s] in registers: lane l -> A[l] (lo) and A[32+l] (hi);
// A[64] is warp-uniform (top). Serial chain per step: shfl_up + FFMA.
// Renormalize every 8 steps (warp max -> scale to ~1), carry C = sum(log m).
// ---------------------------------------------------------------------------
__global__ void __launch_bounds__(128)
alpha_kernel(const int* __restrict__ input_lengths,
             const int* __restrict__ label_lengths,
             float* __restrict__ out)
{
    extern __shared__ float smem[];
    float* eb_s = smem;                 // TM*SP1 = 8320 floats
    float* el_s = smem + TM * SP1;

    const int b   = blockIdx.x;
    const int tid = threadIdx.x;

    // Cooperative staged copy (float4)
    {
        const float4* gb4 = reinterpret_cast<const float4*>(g_eb + (size_t)b * TM * SP1);
        const float4* gl4 = reinterpret_cast<const float4*>(g_el + (size_t)b * TM * SP1);
        float4* sb4 = reinterpret_cast<float4*>(eb_s);
        float4* sl4 = reinterpret_cast<float4*>(el_s);
        constexpr int N4 = TM * SP1 / 4;   // 2080
        for (int i = tid; i < N4; i += 128) {
            sb4[i] = gb4[i];
            sl4[i] = gl4[i];
        }
    }
    __syncthreads();

    if (tid >= 32) return;               // recursion lives in warp 0
    const int l = tid;
    const unsigned FULL = 0xffffffffu;

    const int Tb = input_lengths[b];
    const int Sb = label_lengths[b];

    float A_lo  = (l == 0) ? 1.f : 0.f;  // A[l]
    float A_hi  = 0.f;                   // A[32+l]
    float A_top = 0.f;                   // A[64] (warp-uniform)
    float C     = 0.f;                   // accumulated log scale

#define ALPHA_STEP(T_)                                                        \
    {                                                                         \
        const float* bt = eb_s + (T_) * SP1;                                  \
        const float* lt = el_s + (T_) * SP1;                                  \
        const float eb_lo  = bt[l];                                           \
        const float eb_hi  = bt[l + 32];                                      \
        const float eb_top = bt[64];                                          \
        const float el_m1  = lt[(l == 0) ? 0 : (l - 1)];                      \
        const float el_h   = lt[l + 31];                                      \
        const float el_t   = lt[63];                                          \
        const float pa_lo = __shfl_up_sync(FULL, A_lo, 1);                    \
        const float la_lo = __shfl_sync(FULL, A_lo, 31);                      \
        const float pa_hi = __shfl_up_sync(FULL, A_hi, 1);                    \
        const float la_hi = __shfl_sync(FULL, A_hi, 31);                      \
        const float nb_lo = (l == 0) ? 0.f : pa_lo;                           \
        const float nb_hi = (l == 0) ? la_lo : pa_hi;                         \
        A_lo  = fmaf(nb_lo, el_m1, A_lo * eb_lo);                             \
        A_hi  = fmaf(nb_hi, el_h,  A_hi * eb_hi);                             \
        A_top = fmaf(la_hi, el_t,  A_top * eb_top);                           \
    }

    int t = 0;
    const int nblk = Tb >> 3;
    for (int blk = 0; blk < nblk; blk++) {
#pragma unroll
        for (int k = 0; k < 8; k++) ALPHA_STEP(t + k);
        t += 8;

        // Renormalize: warp max of all A, scale to ~1, accumulate log.
        float mx = fmaxf(A_lo, A_hi);
#pragma unroll
        for (int off = 16; off > 0; off >>= 1)
            mx = fmaxf(mx, __shfl_xor_sync(FULL, mx, off));
        mx = fmaxf(fmaxf(mx, A_top), 1e-35f);
        const float r = 1.0f / mx;
        A_lo *= r;  A_hi *= r;  A_top *= r;
        C += __logf(mx);
    }
    for (; t < Tb; t++) ALPHA_STEP(t);   // tail (no renorm needed)
#undef ALPHA_STEP

    // select A[Sb]
    float res;
    if (Sb >= 64)      res = A_top;
    else if (Sb >= 32) res = __shfl_sync(FULL, A_hi, Sb - 32);
    else               res = __shfl_sync(FULL, A_lo, Sb);

    if (l == 0) out[b] = -(C + __logf(res));
}

// ---------------------------------------------------------------------------
extern "C" void kernel_launch(void* const* d_in, const int* in_sizes, int n_in,
                              void* d_out, int out_size)
{
    const float* acts   = (const float*)d_in[0];
    const int*   labels = (const int*)d_in[1];
    const int*   ilen   = (const int*)d_in[2];
    const int*   llen   = (const int*)d_in[3];
    float*       out    = (float*)d_out;

    const int rows_per_blk = 8;
    const int gridA = (NROWS + rows_per_blk - 1) / rows_per_blk;
    lse_kernel<<<gridA, 256>>>(acts, labels);

    const size_t smemB = (size_t)2 * TM * SP1 * sizeof(float);  // 66560 B
    cudaFuncSetAttribute(alpha_kernel,
                         cudaFuncAttributeMaxDynamicSharedMemorySize,
                         (int)smemB);
    alpha_kernel<<<B, 128, smemB>>>(ilen, llen, out);
}

// round 7
// speedup vs baseline: 1.1426x; 1.0226x over previous
#include <cuda_runtime.h>
#include <cuda_bf16.h>
#include <cstddef>

// Problem constants (fixed by the reference setup)
constexpr int B   = 16;
constexpr int TM  = 128;
constexpr int SM  = 64;
constexpr int SP1 = SM + 1;            // 65
constexpr int V   = 1024;
constexpr int NROWS = B * TM * SP1;    // 133120

// Scratch in EXP space (device globals: no allocation in kernel_launch)
__device__ float g_eb[NROWS];   // exp(blank_lp) per row
__device__ float g_el[NROWS];   // exp(label_lp) per row (0 where s == SM)

// ---------------------------------------------------------------------------
// Kernel A: per-row logsumexp; writes exp-space blank/label probabilities.
// One warp per row; 8x float4 per lane; HBM-bound (~7.1 TB/s achieved).
// ---------------------------------------------------------------------------
__global__ void __launch_bounds__(256)
lse_kernel(const float* __restrict__ acts, const int* __restrict__ labels)
{
    const int warps_per_blk = blockDim.x >> 5;
    const int row  = blockIdx.x * warps_per_blk + (threadIdx.x >> 5);
    const int lane = threadIdx.x & 31;
    if (row >= NROWS) return;

    const float4* p = reinterpret_cast<const float4*>(acts) + (size_t)row * (V / 4);

    float4 v[8];
#pragma unroll
    for (int j = 0; j < 8; j++) v[j] = p[j * 32 + lane];

    float m = v[0].x;
#pragma unroll
    for (int j = 0; j < 8; j++) {
        m = fmaxf(m, fmaxf(fmaxf(v[j].x, v[j].y), fmaxf(v[j].z, v[j].w)));
    }
    float s = 0.f;
#pragma unroll
    for (int j = 0; j < 8; j++) {
        s += __expf(v[j].x - m) + __expf(v[j].y - m)
           + __expf(v[j].z - m) + __expf(v[j].w - m);
    }
#pragma unroll
    for (int off = 16; off > 0; off >>= 1) {
        float mo = __shfl_xor_sync(0xffffffffu, m, off);
        float so = __shfl_xor_sync(0xffffffffu, s, off);
        float M  = fmaxf(m, mo);
        s = s * __expf(m - M) + so * __expf(mo - M);
        m = M;
    }

    if (lane == 0) {
        const float lse = m + __logf(s);
        const int b    = row / (TM * SP1);
        const int rem  = row % (TM * SP1);
        const int sidx = rem % SP1;

        g_eb[row] = __expf(v[0].x - lse);   // exp(blank - lse)

        float el = 0.f;
        if (sidx < SM) {
            const int lab = labels[b * SM + sidx];
            el = __expf(__ldg(acts + (size_t)row * V + lab) - lse);  // L1 hit
        }
        g_el[row] = el;
    }
}

// ---------------------------------------------------------------------------
// Kernel B: alpha recursion in probability space. One CTA per batch.
// Pair layout: lane l holds x = A[2l], y = A[2l+1]; top = A[64] (uniform).
// Per step: one shfl_up(y) feeds x'; y' and top are lane-local FMAs off the
// recurrent shfl, so the shfl cycle spans 2 steps (~17 cyc/step amortized).
// Smem operands block-prefetched into registers (8 steps ahead).
// Renorm NON-DEFERRED every 8 steps (deferral underflows fp32: values reach
// e^-120 before the late correction; 8-step gap keeps them >= ~e^-60).
// ---------------------------------------------------------------------------
__global__ void __launch_bounds__(128)
alpha_kernel(const int* __restrict__ input_lengths,
             const int* __restrict__ label_lengths,
             float* __restrict__ out)
{
    extern __shared__ float smem[];
    float* eb_s = smem;                 // TM*SP1 = 8320 floats
    float* el_s = smem + TM * SP1;

    const int b   = blockIdx.x;
    const int tid = threadIdx.x;

    // Cooperative staged copy (float4)
    {
        const float4* gb4 = reinterpret_cast<const float4*>(g_eb + (size_t)b * TM * SP1);
        const float4* gl4 = reinterpret_cast<const float4*>(g_el + (size_t)b * TM * SP1);
        float4* sb4 = reinterpret_cast<float4*>(eb_s);
        float4* sl4 = reinterpret_cast<float4*>(el_s);
        constexpr int N4 = TM * SP1 / 4;   // 2080
        for (int i = tid; i < N4; i += 128) {
            sb4[i] = gb4[i];
            sl4[i] = gl4[i];
        }
    }
    __syncthreads();

    if (tid >= 32) return;               // recursion lives in warp 0
    const int l = tid;
    const unsigned FULL = 0xffffffffu;

    const int Tb = input_lengths[b];
    const int Sb = label_lengths[b];

    float x   = (l == 0) ? 1.f : 0.f;    // A[2l]
    float y   = 0.f;                     // A[2l+1]
    float top = 0.f;                     // A[64] (warp-uniform)
    float C   = 0.f;                     // accumulated log scale

    // Prefetch buffers for one 8-step block
    float ebx[8], eby[8], ebt[8], elx[8], em1[8], elt[8];

#define LOADBLK(T0)                                                           \
    {                                                                         \
        _Pragma("unroll")                                                     \
        for (int k = 0; k < 8; k++) {                                         \
            const float* bt = eb_s + ((T0) + k) * SP1;                        \
            const float* lt = el_s + ((T0) + k) * SP1;                        \
            ebx[k] = bt[2 * l];                                               \
            eby[k] = bt[2 * l + 1];                                           \
            ebt[k] = bt[64];                                                  \
            elx[k] = lt[2 * l];                                               \
            em1[k] = l ? lt[2 * l - 1] : 0.f;                                 \
            elt[k] = lt[63];                                                  \
        }                                                                     \
    }

#define STEP(K)                                                               \
    {                                                                         \
        const float py = __shfl_up_sync(FULL, y, 1);  /* A[2l-1] */           \
        const float ly = __shfl_sync(FULL, y, 31);    /* A[63]   */           \
        const float nx = fmaf(py, em1[K], x * ebx[K]);                        \
        const float ny = fmaf(x,  elx[K], y * eby[K]);                        \
        top = fmaf(ly, elt[K], top * ebt[K]);                                 \
        x = nx;  y = ny;                                                      \
    }

    int t = 0;
    const int nblk = Tb >> 3;

    for (int blk = 0; blk < nblk; blk++) {
        LOADBLK(t);
        STEP(0); STEP(1); STEP(2); STEP(3);
        STEP(4); STEP(5); STEP(6); STEP(7);
        t += 8;

        // Non-deferred renorm: warp max of all A, scale to ~1, accumulate log
        float M = fmaxf(fmaxf(x, y), top);
#pragma unroll
        for (int off = 16; off > 0; off >>= 1)
            M = fmaxf(M, __shfl_xor_sync(FULL, M, off));
        M = fmaxf(M, 1e-35f);
        const float r = __fdividef(1.0f, M);
        x *= r;  y *= r;  top *= r;
        C += __logf(M);
    }
    // tail (Tb % 8 steps) — direct loads, no renorm
    for (; t < Tb; t++) {
        const float* bt = eb_s + t * SP1;
        const float* lt = el_s + t * SP1;
        const float py = __shfl_up_sync(FULL, y, 1);
        const float ly = __shfl_sync(FULL, y, 31);
        const float e1 = l ? lt[2 * l - 1] : 0.f;
        const float nx = fmaf(py, e1, x * bt[2 * l]);
        const float ny = fmaf(x, lt[2 * l], y * bt[2 * l + 1]);
        top = fmaf(ly, lt[63], top * bt[64]);
        x = nx;  y = ny;
    }
#undef STEP
#undef LOADBLK

    // select A[Sb]:  Sb==64 -> top ; else lane Sb/2, component Sb%2
    float res;
    if (Sb >= 64) res = top;
    else          res = __shfl_sync(FULL, (Sb & 1) ? y : x, Sb >> 1);

    if (l == 0) out[b] = -(C + __logf(res));
}

// ---------------------------------------------------------------------------
extern "C" void kernel_launch(void* const* d_in, const int* in_sizes, int n_in,
                              void* d_out, int out_size)
{
    const float* acts   = (const float*)d_in[0];
    const int*   labels = (const int*)d_in[1];
    const int*   ilen   = (const int*)d_in[2];
    const int*   llen   = (const int*)d_in[3];
    float*       out    = (float*)d_out;

    const int rows_per_blk = 8;
    const int gridA = (NROWS + rows_per_blk - 1) / rows_per_blk;
    lse_kernel<<<gridA, 256>>>(acts, labels);

    const size_t smemB = (size_t)2 * TM * SP1 * sizeof(float);  // 66560 B
    cudaFuncSetAttribute(alpha_kernel,
                         cudaFuncAttributeMaxDynamicSharedMemorySize,
                         (int)smemB);
    alpha_kernel<<<B, 128, smemB>>>(ilen, llen, out);
}